// round 1
// baseline (speedup 1.0000x reference)
#include <cuda_runtime.h>

// VecInt: scaling-and-squaring integration of a stationary velocity field.
//   v0 = vel / 2^7;  repeat 7x: v <- v + trilinear_warp(v, v)
// Shapes: [2, 128, 128, 128, 3] float32 (channel-last, w fastest spatial dim,
// channel 0 displaces along d (slowest), channel 2 along w (fastest)).
//
// Strategy:
//  - 7 kernel launches ping-ponging between two float4-padded __device__
//    scratch volumes (16 B/voxel -> every corner gather is one LDG.128).
//  - Pass 1 reads the packed harness input and folds in the 1/128 scale.
//  - Pass 7 writes packed float32x3 directly to d_out.
//  - 3D thread blocks (32,4,2) for gather locality (L1/L2 reuse).

static constexpr int DIMS  = 128;
static constexpr int NB    = 2;
static constexpr int NVOX  = NB * DIMS * DIMS * DIMS;   // 4,194,304

// Padded scratch volumes (float4 per voxel, .w unused). Static device arrays:
// allowed by the allocation guards. 2 x 67 MB.
__device__ float4 g_bufA[NVOX];
__device__ float4 g_bufB[NVOX];

template<bool IN_PACKED, bool OUT_PACKED>
__global__ __launch_bounds__(256)
void vecint_step(const float*  __restrict__ in_p,   // packed input (pass 1)
                 const float4* __restrict__ in_v,   // padded input (passes 2..7)
                 float*        __restrict__ out_p,  // packed output (pass 7)
                 float4*       __restrict__ out_v,  // padded output (passes 1..6)
                 float scale)                        // 1/128 on pass 1, else 1
{
    const int w  = blockIdx.x * 32 + threadIdx.x;
    const int h  = blockIdx.y * 4  + threadIdx.y;
    const int zb = blockIdx.z;                 // [0,128): 64 d-blocks per batch
    const int b  = zb >> 6;
    const int d  = ((zb & 63) << 1) + threadIdx.z;

    const int base = ((b * DIMS + d) * DIMS + h) * DIMS + w;

    // Own flow vector (this voxel's displacement, already in integrated units)
    float f0, f1, f2;
    if (IN_PACKED) {
        const float* p = in_p + (size_t)base * 3;
        f0 = p[0] * scale; f1 = p[1] * scale; f2 = p[2] * scale;
    } else {
        const float4 v = in_v[base];
        f0 = v.x; f1 = v.y; f2 = v.z;
    }

    // Sample location, border-clipped (matches jnp.clip(grid+flow, 0, dim-1))
    const float ld = fminf(fmaxf((float)d + f0, 0.0f), 127.0f);
    const float lh = fminf(fmaxf((float)h + f1, 0.0f), 127.0f);
    const float lw = fminf(fmaxf((float)w + f2, 0.0f), 127.0f);

    const float fd = floorf(ld), fh = floorf(lh), fw = floorf(lw);
    const int   id0 = (int)fd,  ih0 = (int)fh,  iw0 = (int)fw;
    const float wd1 = ld - fd,  wh1 = lh - fh,  ww1 = lw - fw;
    const float wd0 = 1.0f - wd1, wh0 = 1.0f - wh1, ww0 = 1.0f - ww1;
    const int   id1 = min(id0 + 1, 127);
    const int   ih1 = min(ih0 + 1, 127);
    const int   iw1 = min(iw0 + 1, 127);

    const int bb = b * DIMS * DIMS * DIMS;

    float r0 = 0.0f, r1 = 0.0f, r2 = 0.0f;
#pragma unroll
    for (int cd = 0; cd < 2; ++cd) {
        const int   dd = cd ? id1 : id0;
        const float wd = cd ? wd1 : wd0;
#pragma unroll
        for (int ch = 0; ch < 2; ++ch) {
            const int   hh  = ch ? ih1 : ih0;
            const float wdh = wd * (ch ? wh1 : wh0);
            const int   rowbase = bb + (dd * DIMS + hh) * DIMS;
#pragma unroll
            for (int cw = 0; cw < 2; ++cw) {
                const int   ww  = cw ? iw1 : iw0;
                const float wgt = wdh * (cw ? ww1 : ww0);
                const int   idx = rowbase + ww;
                float v0, v1, v2;
                if (IN_PACKED) {
                    const float* p = in_p + (size_t)idx * 3;
                    v0 = p[0]; v1 = p[1]; v2 = p[2];
                } else {
                    const float4 v = in_v[idx];   // single LDG.128
                    v0 = v.x; v1 = v.y; v2 = v.z;
                }
                r0 += wgt * v0; r1 += wgt * v1; r2 += wgt * v2;
            }
        }
    }
    if (IN_PACKED) { r0 *= scale; r1 *= scale; r2 *= scale; }

    const float o0 = f0 + r0, o1 = f1 + r1, o2 = f2 + r2;
    if (OUT_PACKED) {
        float* p = out_p + (size_t)base * 3;
        p[0] = o0; p[1] = o1; p[2] = o2;
    } else {
        out_v[base] = make_float4(o0, o1, o2, 0.0f);  // single STG.128
    }
}

extern "C" void kernel_launch(void* const* d_in, const int* in_sizes, int n_in,
                              void* d_out, int out_size)
{
    (void)in_sizes; (void)n_in; (void)out_size;
    const float* vel = (const float*)d_in[0];
    float*       out = (float*)d_out;

    float4 *A = nullptr, *B = nullptr;
    cudaGetSymbolAddress((void**)&A, g_bufA);
    cudaGetSymbolAddress((void**)&B, g_bufB);

    const dim3 blk(32, 4, 2);
    const dim3 grd(DIMS / 32, DIMS / 4, (DIMS / 2) * NB);
    const float s = 1.0f / 128.0f;   // 1 / 2^INT_STEPS

    // 7 scaling-and-squaring steps.
    vecint_step<true,  false><<<grd, blk>>>(vel, nullptr, nullptr, A, s);     // 1: in  -> A
    vecint_step<false, false><<<grd, blk>>>(nullptr, A, nullptr, B, 1.0f);    // 2: A -> B
    vecint_step<false, false><<<grd, blk>>>(nullptr, B, nullptr, A, 1.0f);    // 3: B -> A
    vecint_step<false, false><<<grd, blk>>>(nullptr, A, nullptr, B, 1.0f);    // 4: A -> B
    vecint_step<false, false><<<grd, blk>>>(nullptr, B, nullptr, A, 1.0f);    // 5: B -> A
    vecint_step<false, false><<<grd, blk>>>(nullptr, A, nullptr, B, 1.0f);    // 6: A -> B
    vecint_step<false, true ><<<grd, blk>>>(nullptr, B, out, nullptr, 1.0f);  // 7: B -> out
}

// round 2
// speedup vs baseline: 1.6028x; 1.6028x over previous
#include <cuda_runtime.h>
#include <cuda_fp16.h>

// VecInt: scaling-and-squaring integration, 7 steps.
//   v0 = vel / 128;  v <- v + trilinear_warp(v, v)  x7
// [2,128,128,128,3] f32 channel-last.
//
// R2: intermediates stored as fp16x4 (8 B/voxel) to halve the L1tex line
// footprint of the 8-corner gathers (the measured bottleneck: L1 = 87.7%).
// All arithmetic in f32; fp16 only at store (rn). A streaming convert pass
// produces the first fp16 volume (folding the 1/128 scale); the last gather
// pass writes packed f32 straight to d_out.

static constexpr int DIMS = 128;
static constexpr int NB   = 2;
static constexpr int NVOX = NB * DIMS * DIMS * DIMS;   // 4,194,304

// fp16x4-padded scratch volumes (uint2 = 4 halves, .w unused). 2 x 33.5 MB.
__device__ uint2 g_bufA[NVOX];
__device__ uint2 g_bufB[NVOX];

__device__ __forceinline__ void h4_to_f3(uint2 u, float& x, float& y, float& z)
{
    __half2 h01 = *reinterpret_cast<__half2*>(&u.x);
    __half2 h23 = *reinterpret_cast<__half2*>(&u.y);
    float2  f01 = __half22float2(h01);
    x = f01.x; y = f01.y; z = __low2float(h23);
}

__device__ __forceinline__ uint2 f3_to_h4(float x, float y, float z)
{
    __half2 h01 = __floats2half2_rn(x, y);
    __half2 h23 = __floats2half2_rn(z, 0.0f);
    uint2 u;
    u.x = *reinterpret_cast<unsigned int*>(&h01);
    u.y = *reinterpret_cast<unsigned int*>(&h23);
    return u;
}

// Streaming convert: packed f32x3 -> fp16x4, folding scale = 1/128.
// Each thread handles 4 voxels (48 B in = 3 float4 loads, 32 B out).
__global__ __launch_bounds__(256)
void vecint_convert(const float4* __restrict__ in, uint2* __restrict__ out)
{
    const int t = blockIdx.x * blockDim.x + threadIdx.x;   // voxel-quad id
    const float s = 1.0f / 128.0f;
    const float4 a = in[3 * t + 0];
    const float4 b = in[3 * t + 1];
    const float4 c = in[3 * t + 2];
    out[4 * t + 0] = f3_to_h4(a.x * s, a.y * s, a.z * s);
    out[4 * t + 1] = f3_to_h4(a.w * s, b.x * s, b.y * s);
    out[4 * t + 2] = f3_to_h4(b.z * s, b.w * s, c.x * s);
    out[4 * t + 3] = f3_to_h4(c.y * s, c.z * s, c.w * s);
}

template<bool OUT_PACKED>
__global__ __launch_bounds__(256)
void vecint_step(const uint2* __restrict__ in_v,    // fp16x4 input volume
                 float*       __restrict__ out_p,   // packed f32 out (last pass)
                 uint2*       __restrict__ out_v)   // fp16x4 out (other passes)
{
    const int w  = blockIdx.x * 32 + threadIdx.x;
    const int h  = blockIdx.y * 4  + threadIdx.y;
    const int zb = blockIdx.z;
    const int b  = zb >> 6;
    const int d  = ((zb & 63) << 1) + threadIdx.z;

    const int base = ((b * DIMS + d) * DIMS + h) * DIMS + w;

    float f0, f1, f2;
    h4_to_f3(in_v[base], f0, f1, f2);

    const float ld = fminf(fmaxf((float)d + f0, 0.0f), 127.0f);
    const float lh = fminf(fmaxf((float)h + f1, 0.0f), 127.0f);
    const float lw = fminf(fmaxf((float)w + f2, 0.0f), 127.0f);

    const float fd = floorf(ld), fh = floorf(lh), fw = floorf(lw);
    const int   id0 = (int)fd,  ih0 = (int)fh,  iw0 = (int)fw;
    const float wd1 = ld - fd,  wh1 = lh - fh,  ww1 = lw - fw;
    const float wd0 = 1.0f - wd1, wh0 = 1.0f - wh1, ww0 = 1.0f - ww1;
    const int   id1 = min(id0 + 1, 127);
    const int   ih1 = min(ih0 + 1, 127);
    const int   iw1 = min(iw0 + 1, 127);

    const int bb = b * DIMS * DIMS * DIMS;

    float r0 = 0.0f, r1 = 0.0f, r2 = 0.0f;
#pragma unroll
    for (int cd = 0; cd < 2; ++cd) {
        const int   dd = cd ? id1 : id0;
        const float wd = cd ? wd1 : wd0;
#pragma unroll
        for (int ch = 0; ch < 2; ++ch) {
            const int   hh  = ch ? ih1 : ih0;
            const float wdh = wd * (ch ? wh1 : wh0);
            const int   rowbase = bb + (dd * DIMS + hh) * DIMS;
#pragma unroll
            for (int cw = 0; cw < 2; ++cw) {
                const int   ww  = cw ? iw1 : iw0;
                const float wgt = wdh * (cw ? ww1 : ww0);
                float v0, v1, v2;
                h4_to_f3(in_v[rowbase + ww], v0, v1, v2);   // one LDG.64
                r0 = fmaf(wgt, v0, r0);
                r1 = fmaf(wgt, v1, r1);
                r2 = fmaf(wgt, v2, r2);
            }
        }
    }

    const float o0 = f0 + r0, o1 = f1 + r1, o2 = f2 + r2;
    if (OUT_PACKED) {
        float* p = out_p + (size_t)base * 3;
        p[0] = o0; p[1] = o1; p[2] = o2;
    } else {
        out_v[base] = f3_to_h4(o0, o1, o2);                 // one STG.64
    }
}

extern "C" void kernel_launch(void* const* d_in, const int* in_sizes, int n_in,
                              void* d_out, int out_size)
{
    (void)in_sizes; (void)n_in; (void)out_size;
    const float4* vel = (const float4*)d_in[0];
    float*        out = (float*)d_out;

    uint2 *A = nullptr, *B = nullptr;
    cudaGetSymbolAddress((void**)&A, g_bufA);
    cudaGetSymbolAddress((void**)&B, g_bufB);

    // Pass 0: convert + scale (NVOX/4 voxel-quads, 256 thr/block).
    vecint_convert<<<NVOX / 4 / 256, 256>>>(vel, A);

    const dim3 blk(32, 4, 2);
    const dim3 grd(DIMS / 32, DIMS / 4, (DIMS / 2) * NB);

    vecint_step<false><<<grd, blk>>>(A, nullptr, B);   // 1
    vecint_step<false><<<grd, blk>>>(B, nullptr, A);   // 2
    vecint_step<false><<<grd, blk>>>(A, nullptr, B);   // 3
    vecint_step<false><<<grd, blk>>>(B, nullptr, A);   // 4
    vecint_step<false><<<grd, blk>>>(A, nullptr, B);   // 5
    vecint_step<false><<<grd, blk>>>(B, nullptr, A);   // 6
    vecint_step<true ><<<grd, blk>>>(A, out, nullptr); // 7 -> packed f32 out
}